// round 12
// baseline (speedup 1.0000x reference)
#include <cuda_runtime.h>
#include <cuda_fp16.h>
#include <cstddef>

#define NMAX 100000
#define EMAX 1600000
#define NCHUNK_MAX ((NMAX + 1023) / 1024 + 1)

// Scratch (__device__ globals; allocation-free rule; zero-initialized at load)
__device__ __half g_f1h[NMAX * 64];   // features @ W1 (fp16 storage)
__device__ __half g_f2h[NMAX * 32];   // relu(agg + b1) @ W2 (fp16 storage)
__device__ int    g_cnt[NMAX];        // in-degree histogram (self-restoring to 0)
__device__ int    g_rs[NMAX + 4];     // CSR row starts
__device__ int    g_cur[NMAX + 4];    // placement cursors
__device__ int    g_esrc[EMAX];       // CSR src lists grouped by dst
__device__ int    g_bsum[NCHUNK_MAX]; // per-1024-chunk sums
__device__ int    g_flag[NCHUNK_MAX]; // publish flags (reset by place_kernel)

#define FMA2(acc_, a_, b_) \
    asm("fma.rn.f32x2 %0, %1, %2, %0;" : "+l"(acc_) : "l"(a_), "l"(b_))

// Packed fp16 pairwise add: 4 values per instruction
__device__ __forceinline__ int4 hadd2_int4(int4 a, int4 b) {
    int4 r;
    asm("add.rn.f16x2 %0, %1, %2;" : "=r"(r.x) : "r"(a.x), "r"(b.x));
    asm("add.rn.f16x2 %0, %1, %2;" : "=r"(r.y) : "r"(a.y), "r"(b.y));
    asm("add.rn.f16x2 %0, %1, %2;" : "=r"(r.z) : "r"(a.z), "r"(b.z));
    asm("add.rn.f16x2 %0, %1, %2;" : "=r"(r.w) : "r"(a.w), "r"(b.w));
    return r;
}

// ---------------------------------------------------------------------------
// Fused: transform1 (blocks [0, tb)) + histogram (blocks [tb, tb+hb)).
// ---------------------------------------------------------------------------
__global__ __launch_bounds__(128) void t1_hist_kernel(
    const float* __restrict__ X, const float* __restrict__ W,
    __half* __restrict__ Y, const int* __restrict__ dst,
    int n, int n_edges, int tb) {
    __shared__ float As[128 * 64];
    __shared__ float Ws[64 * 64];
    int tid = threadIdx.x;

    if (blockIdx.x >= tb) {
        // ---- histogram part: 8 edges/thread fire-and-forget REDs ----
        int hb = blockIdx.x - tb;
        int base = (hb * 128 + tid) * 8;
        if (base + 8 <= n_edges) {
            int4 d0 = *(const int4*)(dst + base);
            int4 d1 = *(const int4*)(dst + base + 4);
            atomicAdd(&g_cnt[d0.x], 1); atomicAdd(&g_cnt[d0.y], 1);
            atomicAdd(&g_cnt[d0.z], 1); atomicAdd(&g_cnt[d0.w], 1);
            atomicAdd(&g_cnt[d1.x], 1); atomicAdd(&g_cnt[d1.y], 1);
            atomicAdd(&g_cnt[d1.z], 1); atomicAdd(&g_cnt[d1.w], 1);
        } else {
            for (int j = 0; j < 8; j++)
                if (base + j < n_edges) atomicAdd(&g_cnt[dst[base + j]], 1);
        }
        return;
    }

    // ---- transform part: 128-row tile, thread = 8 rows x 8 cols ----
    for (int i = tid; i < 64 * 64; i += 128) Ws[i] = W[i];
    __syncthreads();

    int blk = blockIdx.x * 128;
#pragma unroll
    for (int i = 0; i < 16; i++) {
        int idx = i * 128 + tid;
        int row = idx >> 4, c = idx & 15;
        int gr = blk + row;
        float4 v = make_float4(0.f, 0.f, 0.f, 0.f);
        if (gr < n) v = *(const float4*)(X + (size_t)gr * 64 + c * 4);
        float vv[4] = {v.x, v.y, v.z, v.w};
        int rm = row & 31;
#pragma unroll
        for (int j = 0; j < 4; j++)
            As[row * 64 + ((c * 4 + j) ^ rm)] = vv[j];
    }
    __syncthreads();

    int tr = tid >> 3, tc = tid & 7;
    unsigned long long acc[8][4];
#pragma unroll
    for (int r = 0; r < 8; r++)
#pragma unroll
        for (int p = 0; p < 4; p++) acc[r][p] = 0ULL;

    int rowoff[8], rmask[8];
#pragma unroll
    for (int r = 0; r < 8; r++) {
        int row = tr * 8 + r;
        rowoff[r] = row * 64;
        rmask[r] = row & 31;
    }

#pragma unroll 4
    for (int k = 0; k < 64; k++) {
        unsigned long long b[4];
#pragma unroll
        for (int p = 0; p < 4; p++)
            b[p] = *(const unsigned long long*)(Ws + k * 64 + tc * 8 + 2 * p);
#pragma unroll
        for (int r = 0; r < 8; r++) {
            float a = As[rowoff[r] + (k ^ rmask[r])];
            unsigned int au = __float_as_uint(a);
            unsigned long long a2;
            asm("mov.b64 %0, {%1, %1};" : "=l"(a2) : "r"(au));
#pragma unroll
            for (int p = 0; p < 4; p++) FMA2(acc[r][p], a2, b[p]);
        }
    }

#pragma unroll
    for (int r = 0; r < 8; r++) {
        int gr = blk + tr * 8 + r;
        if (gr >= n) continue;
        __half* yr = Y + (size_t)gr * 64 + tc * 8;
        unsigned int h[4];
#pragma unroll
        for (int p = 0; p < 4; p++) {
            unsigned int lo, hi;
            asm("mov.b64 {%0, %1}, %2;" : "=r"(lo), "=r"(hi) : "l"(acc[r][p]));
            __half2 hp = __floats2half2_rn(__uint_as_float(lo), __uint_as_float(hi));
            h[p] = *(unsigned int*)&hp;
        }
        *(int4*)yr = make_int4((int)h[0], (int)h[1], (int)h[2], (int)h[3]);
    }
}

// ---------------------------------------------------------------------------
// Single-pass scan: publish chunk sum, spin for predecessors, write rs/cur,
// re-zero own cnt chunk. Grid = nchunk (<=99) < #SMs -> spin is safe.
// ---------------------------------------------------------------------------
__global__ __launch_bounds__(256) void scan_all_kernel(int n, int n_edges) {
    __shared__ int red[256];
    __shared__ int ws[8];
    int b = blockIdx.x, t = threadIdx.x;
    int i = b * 1024 + t * 4;

    int4 v = make_int4(0, 0, 0, 0);
    bool full = (i + 3 < n);
    if (full) {
        v = *(const int4*)(g_cnt + i);
        *(int4*)(g_cnt + i) = make_int4(0, 0, 0, 0);
    } else {
        int tmp[4] = {0, 0, 0, 0};
        for (int j = 0; j < 4; j++)
            if (i + j < n) { tmp[j] = g_cnt[i + j]; g_cnt[i + j] = 0; }
        v = make_int4(tmp[0], tmp[1], tmp[2], tmp[3]);
    }
    int tsum = (v.x + v.y) + (v.z + v.w);

    red[t] = tsum;
    __syncthreads();
    for (int off = 128; off > 0; off >>= 1) {
        if (t < off) red[t] += red[t + off];
        __syncthreads();
    }
    if (t == 0) {
        g_bsum[b] = red[0];
        __threadfence();
        atomicExch(&g_flag[b], 1);
    }
    __syncthreads();

    int lane = t & 31, wid = t >> 5;
    int p = tsum;
#pragma unroll
    for (int o = 1; o < 32; o <<= 1) {
        int x = __shfl_up_sync(0xffffffffu, p, o);
        if (lane >= o) p += x;
    }
    if (lane == 31) ws[wid] = p;
    __syncthreads();
    if (t == 0) {
        int r = 0;
        for (int w = 0; w < 8; w++) { int x = ws[w]; ws[w] = r; r += x; }
    }
    __syncthreads();

    int part = 0;
    if (t < b) {
        while (atomicAdd(&g_flag[t], 0) == 0) {}
        __threadfence();
        part = g_bsum[t];
    }
    red[t] = part;
    __syncthreads();
    for (int off = 128; off > 0; off >>= 1) {
        if (t < off) red[t] += red[t + off];
        __syncthreads();
    }
    int base = red[0];

    int ex = (p - tsum) + ws[wid] + base;
    int4 pre;
    pre.x = ex;
    pre.y = ex + v.x;
    pre.z = pre.y + v.y;
    pre.w = pre.z + v.z;
    if (full) {
        *(int4*)(g_rs + i) = pre;
        *(int4*)(g_cur + i) = pre;
    } else {
        int pr[4] = {pre.x, pre.y, pre.z, pre.w};
        for (int j = 0; j < 4; j++)
            if (i + j < n) { g_rs[i + j] = pr[j]; g_cur[i + j] = pr[j]; }
    }
    if (b == 0 && t == 0) g_rs[n] = n_edges;
}

// ---------------------------------------------------------------------------
// Placement: 8 edges/thread; also resets g_flag for next replay.
// ---------------------------------------------------------------------------
__global__ void place_kernel(const int* __restrict__ src,
                             const int* __restrict__ dst, int n_edges) {
    if (blockIdx.x == 0 && threadIdx.x < NCHUNK_MAX) g_flag[threadIdx.x] = 0;
    int base = (blockIdx.x * blockDim.x + threadIdx.x) * 8;
    if (base + 8 <= n_edges) {
        int4 d0 = *(const int4*)(dst + base);
        int4 d1 = *(const int4*)(dst + base + 4);
        int4 s0 = *(const int4*)(src + base);
        int4 s1 = *(const int4*)(src + base + 4);
        int dd[8] = {d0.x, d0.y, d0.z, d0.w, d1.x, d1.y, d1.z, d1.w};
        int ss[8] = {s0.x, s0.y, s0.z, s0.w, s1.x, s1.y, s1.z, s1.w};
#pragma unroll
        for (int j = 0; j < 8; j++) {
            int p = atomicAdd(&g_cur[dd[j]], 1);
            g_esrc[p] = ss[j];
        }
    } else {
        for (int j = 0; j < 8; j++) {
            int e = base + j;
            if (e < n_edges) {
                int p = atomicAdd(&g_cur[dst[e]], 1);
                g_esrc[p] = src[e];
            }
        }
    }
}

// Accumulate 8 halves (int4) into 8 fp32 accumulators
__device__ __forceinline__ void acc8h(float* acc, int4 v) {
    __half2 h0 = *(__half2*)&v.x, h1 = *(__half2*)&v.y;
    __half2 h2 = *(__half2*)&v.z, h3 = *(__half2*)&v.w;
    float2 f0 = __half22float2(h0), f1 = __half22float2(h1);
    float2 f2 = __half22float2(h2), f3 = __half22float2(h3);
    acc[0] += f0.x; acc[1] += f0.y; acc[2] += f1.x; acc[3] += f1.y;
    acc[4] += f2.x; acc[5] += f2.y; acc[6] += f3.x; acc[7] += f3.y;
}

// ---------------------------------------------------------------------------
// Fused layer 2: block = 256 thr = 32 nodes x 8 lanes. Per node: gather 64
// fp16 feats (8 edges in flight, two-level fp16 pairwise tree -> 2 int4,
// fp32 accumulate), relu(+b1) -> smem row (stride 68), then 8 lanes x 4
// output cols via FFMA2 vs smem W2; store fp16.
// ---------------------------------------------------------------------------
#define NSTRIDE 68
__global__ __launch_bounds__(256) void fused_layer2_kernel(
    const __half* __restrict__ F, const float* __restrict__ W2,
    const float* __restrict__ b1, __half* __restrict__ Y, int n) {
    __shared__ float Ns[32 * NSTRIDE];
    __shared__ float Ws[64 * 32];
    __shared__ float bs[64];

    int tid = threadIdx.x;
    for (int i = tid; i < 64 * 32; i += 256) Ws[i] = W2[i];
    if (tid < 64) bs[tid] = b1[tid];
    __syncthreads();

    int nl = tid >> 3;          // local node 0..31
    int lane = tid & 7;         // 8 lanes per node
    int node = blockIdx.x * 32 + nl;

    float acc[8];
#pragma unroll
    for (int j = 0; j < 8; j++) acc[j] = 0.f;

    if (node < n) {
        int s = g_rs[node], e = g_rs[node + 1];
        int i = s;
        for (; i + 8 <= e; i += 8) {    // 8 independent LDG.128 in flight
            int ss[8];
#pragma unroll
            for (int j = 0; j < 8; j++) ss[j] = __ldg(g_esrc + i + j);
            int4 v[8];
#pragma unroll
            for (int j = 0; j < 8; j++)
                v[j] = *(const int4*)(F + (size_t)ss[j] * 64 + lane * 8);
            // two-level fp16 tree: 8 -> 4 -> 2, then fp32 accumulate
            int4 p0 = hadd2_int4(v[0], v[1]);
            int4 p1 = hadd2_int4(v[2], v[3]);
            int4 p2 = hadd2_int4(v[4], v[5]);
            int4 p3 = hadd2_int4(v[6], v[7]);
            int4 q0 = hadd2_int4(p0, p1);
            int4 q1 = hadd2_int4(p2, p3);
            acc8h(acc, q0);
            acc8h(acc, q1);
        }
        for (; i + 4 <= e; i += 4) {    // one-level tree for the 4-tail
            int s0 = __ldg(g_esrc + i),     s1 = __ldg(g_esrc + i + 1);
            int s2 = __ldg(g_esrc + i + 2), s3 = __ldg(g_esrc + i + 3);
            int4 v0 = *(const int4*)(F + (size_t)s0 * 64 + lane * 8);
            int4 v1 = *(const int4*)(F + (size_t)s1 * 64 + lane * 8);
            int4 v2 = *(const int4*)(F + (size_t)s2 * 64 + lane * 8);
            int4 v3 = *(const int4*)(F + (size_t)s3 * 64 + lane * 8);
            int4 p0 = hadd2_int4(v0, v1);
            int4 p1 = hadd2_int4(v2, v3);
            acc8h(acc, p0);
            acc8h(acc, p1);
        }
        for (; i < e; i++) {
            int si = __ldg(g_esrc + i);
            int4 v = *(const int4*)(F + (size_t)si * 64 + lane * 8);
            acc8h(acc, v);
        }
    }
    {
        float* row = Ns + nl * NSTRIDE + lane * 8;
#pragma unroll
        for (int j = 0; j < 8; j++)
            row[j] = fmaxf(acc[j] + bs[lane * 8 + j], 0.f);
    }
    __syncthreads();

    // Phase 2: y[node][lane*4 .. +3] = h[node] @ W2 columns (FFMA2),
    // hrow loaded as float4 per 4 k (LDS.128 broadcast).
    unsigned long long oacc[2] = {0ULL, 0ULL};
    const float* hrow = Ns + nl * NSTRIDE;
#pragma unroll 4
    for (int k = 0; k < 64; k += 4) {
        float4 hv = *(const float4*)(hrow + k);
        float ha[4] = {hv.x, hv.y, hv.z, hv.w};
#pragma unroll
        for (int kk = 0; kk < 4; kk++) {
            unsigned int au = __float_as_uint(ha[kk]);
            unsigned long long a2;
            asm("mov.b64 %0, {%1, %1};" : "=l"(a2) : "r"(au));
            unsigned long long w0 =
                *(const unsigned long long*)(Ws + (k + kk) * 32 + lane * 4);
            unsigned long long w1 =
                *(const unsigned long long*)(Ws + (k + kk) * 32 + lane * 4 + 2);
            FMA2(oacc[0], a2, w0);
            FMA2(oacc[1], a2, w1);
        }
    }
    if (node < n) {
        unsigned int l0, h0, l1, h1;
        asm("mov.b64 {%0, %1}, %2;" : "=r"(l0), "=r"(h0) : "l"(oacc[0]));
        asm("mov.b64 {%0, %1}, %2;" : "=r"(l1), "=r"(h1) : "l"(oacc[1]));
        __half2 p0 = __floats2half2_rn(__uint_as_float(l0), __uint_as_float(h0));
        __half2 p1 = __floats2half2_rn(__uint_as_float(l1), __uint_as_float(h1));
        __half* yr = Y + (size_t)node * 32 + lane * 4;
        *(int2*)yr = make_int2(*(int*)&p0, *(int*)&p1);
    }
}

// ---------------------------------------------------------------------------
// Final gather: 4 lanes x 8 halves per node, b2-init, 8 edges in flight,
// two-level fp16 tree, fp32 float4 stores.
// ---------------------------------------------------------------------------
__global__ void gather32h_kernel(const __half* __restrict__ F,
                                 const float* __restrict__ b2,
                                 float* __restrict__ O, int n) {
    int g = blockIdx.x * blockDim.x + threadIdx.x;
    int node = g >> 2, lane = g & 3;
    if (node >= n) return;
    int s = g_rs[node], e = g_rs[node + 1];
    float acc[8];
    {
        float4 blo = *(const float4*)(b2 + lane * 8);
        float4 bhi = *(const float4*)(b2 + lane * 8 + 4);
        acc[0] = blo.x; acc[1] = blo.y; acc[2] = blo.z; acc[3] = blo.w;
        acc[4] = bhi.x; acc[5] = bhi.y; acc[6] = bhi.z; acc[7] = bhi.w;
    }
    int i = s;
    for (; i + 8 <= e; i += 8) {    // 8 independent LDG.128 in flight
        int ss[8];
#pragma unroll
        for (int j = 0; j < 8; j++) ss[j] = __ldg(g_esrc + i + j);
        int4 v[8];
#pragma unroll
        for (int j = 0; j < 8; j++)
            v[j] = *(const int4*)(F + (size_t)ss[j] * 32 + lane * 8);
        int4 p0 = hadd2_int4(v[0], v[1]);
        int4 p1 = hadd2_int4(v[2], v[3]);
        int4 p2 = hadd2_int4(v[4], v[5]);
        int4 p3 = hadd2_int4(v[6], v[7]);
        int4 q0 = hadd2_int4(p0, p1);
        int4 q1 = hadd2_int4(p2, p3);
        acc8h(acc, q0);
        acc8h(acc, q1);
    }
    for (; i + 4 <= e; i += 4) {
        int s0 = __ldg(g_esrc + i),     s1 = __ldg(g_esrc + i + 1);
        int s2 = __ldg(g_esrc + i + 2), s3 = __ldg(g_esrc + i + 3);
        int4 v0 = *(const int4*)(F + (size_t)s0 * 32 + lane * 8);
        int4 v1 = *(const int4*)(F + (size_t)s1 * 32 + lane * 8);
        int4 v2 = *(const int4*)(F + (size_t)s2 * 32 + lane * 8);
        int4 v3 = *(const int4*)(F + (size_t)s3 * 32 + lane * 8);
        int4 p0 = hadd2_int4(v0, v1);
        int4 p1 = hadd2_int4(v2, v3);
        acc8h(acc, p0);
        acc8h(acc, p1);
    }
    for (; i < e; i++) {
        int si = __ldg(g_esrc + i);
        int4 v = *(const int4*)(F + (size_t)si * 32 + lane * 8);
        acc8h(acc, v);
    }
    float* op = O + (size_t)node * 32 + lane * 8;
    *(float4*)op       = make_float4(acc[0], acc[1], acc[2], acc[3]);
    *(float4*)(op + 4) = make_float4(acc[4], acc[5], acc[6], acc[7]);
}

// ---------------------------------------------------------------------------
// kernel_launch (5 launches)
// ---------------------------------------------------------------------------
extern "C" void kernel_launch(void* const* d_in, const int* in_sizes, int n_in,
                              void* d_out, int out_size) {
    const float* features = (const float*)d_in[0];
    const int*   src      = (const int*)d_in[1];
    const int*   dst      = (const int*)d_in[2];
    const float* W1       = (const float*)d_in[3];
    const float* b1       = (const float*)d_in[4];
    const float* W2       = (const float*)d_in[5];
    const float* b2       = (const float*)d_in[6];
    float*       out      = (float*)d_out;

    int n_nodes = in_sizes[0] / 64;
    int n_edges = in_sizes[1];

    void *pf1, *pf2;
    cudaGetSymbolAddress(&pf1, g_f1h);
    cudaGetSymbolAddress(&pf2, g_f2h);
    __half* f1h = (__half*)pf1;
    __half* f2h = (__half*)pf2;

    int nchunk = (n_nodes + 1023) / 1024;
    int tb = (n_nodes + 127) / 128;
    int hb = (n_edges + 1023) / 1024;  // 128 thr * 8 edges

    // 1) transform1 + histogram (independent; overlapped in one launch)
    t1_hist_kernel<<<tb + hb, 128>>>(features, W1, f1h, dst, n_nodes, n_edges, tb);

    // 2) single-pass scan -> rs/cur (also restores cnt to 0)
    scan_all_kernel<<<nchunk, 256>>>(n_nodes, n_edges);

    // 3) placement (also resets scan flags)
    {
        int nthr = (n_edges + 7) / 8;
        place_kernel<<<(nthr + 255) / 256, 256>>>(src, dst, n_edges);
    }

    // 4) fused layer 2: gather f1h -> relu(+b1) -> @W2 -> f2h
    fused_layer2_kernel<<<(n_nodes + 31) / 32, 256>>>(f1h, W2, b1, f2h, n_nodes);

    // 5) out = b2 + segment_sum(f2h[src] -> dst)
    gather32h_kernel<<<(n_nodes * 4 + 255) / 256, 256>>>(f2h, b2, out, n_nodes);
}

// round 13
// speedup vs baseline: 1.1042x; 1.1042x over previous
#include <cuda_runtime.h>
#include <cuda_fp16.h>
#include <cstddef>

#define NMAX 100000
#define EMAX 1600000
#define NCHUNK_MAX ((NMAX + 1023) / 1024 + 1)

// Scratch (__device__ globals; allocation-free rule; zero-initialized at load)
__device__ __half g_f1h[NMAX * 64];   // features @ W1 (fp16 storage)
__device__ __half g_f2h[NMAX * 32];   // relu(agg + b1) @ W2 (fp16 storage)
__device__ int    g_cnt[NMAX];        // in-degree histogram (self-restoring to 0)
__device__ int    g_rs[NMAX + 4];     // CSR row starts
__device__ int    g_cur[NMAX + 4];    // placement cursors
__device__ int    g_esrc[EMAX];       // CSR src lists grouped by dst
__device__ int    g_bsum[NCHUNK_MAX]; // per-1024-chunk sums
__device__ int    g_flag[NCHUNK_MAX]; // publish flags (reset by place_kernel)

#define FMA2(acc_, a_, b_) \
    asm("fma.rn.f32x2 %0, %1, %2, %0;" : "+l"(acc_) : "l"(a_), "l"(b_))

// Packed fp16 pairwise add: 4 values per instruction
__device__ __forceinline__ int4 hadd2_int4(int4 a, int4 b) {
    int4 r;
    asm("add.rn.f16x2 %0, %1, %2;" : "=r"(r.x) : "r"(a.x), "r"(b.x));
    asm("add.rn.f16x2 %0, %1, %2;" : "=r"(r.y) : "r"(a.y), "r"(b.y));
    asm("add.rn.f16x2 %0, %1, %2;" : "=r"(r.z) : "r"(a.z), "r"(b.z));
    asm("add.rn.f16x2 %0, %1, %2;" : "=r"(r.w) : "r"(a.w), "r"(b.w));
    return r;
}

// Accumulate 8 halves (int4) into 8 fp32 accumulators
__device__ __forceinline__ void acc8h(float* acc, int4 v) {
    __half2 h0 = *(__half2*)&v.x, h1 = *(__half2*)&v.y;
    __half2 h2 = *(__half2*)&v.z, h3 = *(__half2*)&v.w;
    float2 f0 = __half22float2(h0), f1 = __half22float2(h1);
    float2 f2 = __half22float2(h2), f3 = __half22float2(h3);
    acc[0] += f0.x; acc[1] += f0.y; acc[2] += f1.x; acc[3] += f1.y;
    acc[4] += f2.x; acc[5] += f2.y; acc[6] += f3.x; acc[7] += f3.y;
}

// ---------------------------------------------------------------------------
// Fused: transform1 (blocks [0, tb)) + histogram (blocks [tb, tb+hb)).
// ---------------------------------------------------------------------------
__global__ __launch_bounds__(128) void t1_hist_kernel(
    const float* __restrict__ X, const float* __restrict__ W,
    __half* __restrict__ Y, const int* __restrict__ dst,
    int n, int n_edges, int tb) {
    __shared__ float As[128 * 64];
    __shared__ float Ws[64 * 64];
    int tid = threadIdx.x;

    if (blockIdx.x >= tb) {
        // ---- histogram part: 8 edges/thread fire-and-forget REDs ----
        int hb = blockIdx.x - tb;
        int base = (hb * 128 + tid) * 8;
        if (base + 8 <= n_edges) {
            int4 d0 = *(const int4*)(dst + base);
            int4 d1 = *(const int4*)(dst + base + 4);
            atomicAdd(&g_cnt[d0.x], 1); atomicAdd(&g_cnt[d0.y], 1);
            atomicAdd(&g_cnt[d0.z], 1); atomicAdd(&g_cnt[d0.w], 1);
            atomicAdd(&g_cnt[d1.x], 1); atomicAdd(&g_cnt[d1.y], 1);
            atomicAdd(&g_cnt[d1.z], 1); atomicAdd(&g_cnt[d1.w], 1);
        } else {
            for (int j = 0; j < 8; j++)
                if (base + j < n_edges) atomicAdd(&g_cnt[dst[base + j]], 1);
        }
        return;
    }

    // ---- transform part: 128-row tile, thread = 8 rows x 8 cols ----
    for (int i = tid; i < 64 * 64; i += 128) Ws[i] = W[i];
    __syncthreads();

    int blk = blockIdx.x * 128;
#pragma unroll
    for (int i = 0; i < 16; i++) {
        int idx = i * 128 + tid;
        int row = idx >> 4, c = idx & 15;
        int gr = blk + row;
        float4 v = make_float4(0.f, 0.f, 0.f, 0.f);
        if (gr < n) v = *(const float4*)(X + (size_t)gr * 64 + c * 4);
        float vv[4] = {v.x, v.y, v.z, v.w};
        int rm = row & 31;
#pragma unroll
        for (int j = 0; j < 4; j++)
            As[row * 64 + ((c * 4 + j) ^ rm)] = vv[j];
    }
    __syncthreads();

    int tr = tid >> 3, tc = tid & 7;
    unsigned long long acc[8][4];
#pragma unroll
    for (int r = 0; r < 8; r++)
#pragma unroll
        for (int p = 0; p < 4; p++) acc[r][p] = 0ULL;

    int rowoff[8], rmask[8];
#pragma unroll
    for (int r = 0; r < 8; r++) {
        int row = tr * 8 + r;
        rowoff[r] = row * 64;
        rmask[r] = row & 31;
    }

#pragma unroll 4
    for (int k = 0; k < 64; k++) {
        unsigned long long b[4];
#pragma unroll
        for (int p = 0; p < 4; p++)
            b[p] = *(const unsigned long long*)(Ws + k * 64 + tc * 8 + 2 * p);
#pragma unroll
        for (int r = 0; r < 8; r++) {
            float a = As[rowoff[r] + (k ^ rmask[r])];
            unsigned int au = __float_as_uint(a);
            unsigned long long a2;
            asm("mov.b64 %0, {%1, %1};" : "=l"(a2) : "r"(au));
#pragma unroll
            for (int p = 0; p < 4; p++) FMA2(acc[r][p], a2, b[p]);
        }
    }

#pragma unroll
    for (int r = 0; r < 8; r++) {
        int gr = blk + tr * 8 + r;
        if (gr >= n) continue;
        __half* yr = Y + (size_t)gr * 64 + tc * 8;
        unsigned int h[4];
#pragma unroll
        for (int p = 0; p < 4; p++) {
            unsigned int lo, hi;
            asm("mov.b64 {%0, %1}, %2;" : "=r"(lo), "=r"(hi) : "l"(acc[r][p]));
            __half2 hp = __floats2half2_rn(__uint_as_float(lo), __uint_as_float(hi));
            h[p] = *(unsigned int*)&hp;
        }
        *(int4*)yr = make_int4((int)h[0], (int)h[1], (int)h[2], (int)h[3]);
    }
}

// ---------------------------------------------------------------------------
// Single-pass scan: publish chunk sum, spin for predecessors, write rs/cur,
// re-zero own cnt chunk. Grid = nchunk (<=99) < #SMs -> spin is safe.
// ---------------------------------------------------------------------------
__global__ __launch_bounds__(256) void scan_all_kernel(int n, int n_edges) {
    __shared__ int red[256];
    __shared__ int ws[8];
    int b = blockIdx.x, t = threadIdx.x;
    int i = b * 1024 + t * 4;

    int4 v = make_int4(0, 0, 0, 0);
    bool full = (i + 3 < n);
    if (full) {
        v = *(const int4*)(g_cnt + i);
        *(int4*)(g_cnt + i) = make_int4(0, 0, 0, 0);
    } else {
        int tmp[4] = {0, 0, 0, 0};
        for (int j = 0; j < 4; j++)
            if (i + j < n) { tmp[j] = g_cnt[i + j]; g_cnt[i + j] = 0; }
        v = make_int4(tmp[0], tmp[1], tmp[2], tmp[3]);
    }
    int tsum = (v.x + v.y) + (v.z + v.w);

    red[t] = tsum;
    __syncthreads();
    for (int off = 128; off > 0; off >>= 1) {
        if (t < off) red[t] += red[t + off];
        __syncthreads();
    }
    if (t == 0) {
        g_bsum[b] = red[0];
        __threadfence();
        atomicExch(&g_flag[b], 1);
    }
    __syncthreads();

    int lane = t & 31, wid = t >> 5;
    int p = tsum;
#pragma unroll
    for (int o = 1; o < 32; o <<= 1) {
        int x = __shfl_up_sync(0xffffffffu, p, o);
        if (lane >= o) p += x;
    }
    if (lane == 31) ws[wid] = p;
    __syncthreads();
    if (t == 0) {
        int r = 0;
        for (int w = 0; w < 8; w++) { int x = ws[w]; ws[w] = r; r += x; }
    }
    __syncthreads();

    int part = 0;
    if (t < b) {
        while (atomicAdd(&g_flag[t], 0) == 0) {}
        __threadfence();
        part = g_bsum[t];
    }
    red[t] = part;
    __syncthreads();
    for (int off = 128; off > 0; off >>= 1) {
        if (t < off) red[t] += red[t + off];
        __syncthreads();
    }
    int base = red[0];

    int ex = (p - tsum) + ws[wid] + base;
    int4 pre;
    pre.x = ex;
    pre.y = ex + v.x;
    pre.z = pre.y + v.y;
    pre.w = pre.z + v.z;
    if (full) {
        *(int4*)(g_rs + i) = pre;
        *(int4*)(g_cur + i) = pre;
    } else {
        int pr[4] = {pre.x, pre.y, pre.z, pre.w};
        for (int j = 0; j < 4; j++)
            if (i + j < n) { g_rs[i + j] = pr[j]; g_cur[i + j] = pr[j]; }
    }
    if (b == 0 && t == 0) g_rs[n] = n_edges;
}

// ---------------------------------------------------------------------------
// Placement: 8 edges/thread; also resets g_flag for next replay.
// ---------------------------------------------------------------------------
__global__ void place_kernel(const int* __restrict__ src,
                             const int* __restrict__ dst, int n_edges) {
    if (blockIdx.x == 0 && threadIdx.x < NCHUNK_MAX) g_flag[threadIdx.x] = 0;
    int base = (blockIdx.x * blockDim.x + threadIdx.x) * 8;
    if (base + 8 <= n_edges) {
        int4 d0 = *(const int4*)(dst + base);
        int4 d1 = *(const int4*)(dst + base + 4);
        int4 s0 = *(const int4*)(src + base);
        int4 s1 = *(const int4*)(src + base + 4);
        int dd[8] = {d0.x, d0.y, d0.z, d0.w, d1.x, d1.y, d1.z, d1.w};
        int ss[8] = {s0.x, s0.y, s0.z, s0.w, s1.x, s1.y, s1.z, s1.w};
#pragma unroll
        for (int j = 0; j < 8; j++) {
            int p = atomicAdd(&g_cur[dd[j]], 1);
            g_esrc[p] = ss[j];
        }
    } else {
        for (int j = 0; j < 8; j++) {
            int e = base + j;
            if (e < n_edges) {
                int p = atomicAdd(&g_cur[dst[e]], 1);
                g_esrc[p] = src[e];
            }
        }
    }
}

// ---------------------------------------------------------------------------
// Fused layer 2: block = 256 thr = 32 nodes x 8 lanes. Gather with 4-edge
// groups (unroll 2 -> 8 LDGs in flight), ONE-level fp16 pairing (register-
// cheap), fp32 accumulate; relu(+b1) -> smem row (stride 68); then 8 lanes
// x 4 output cols via FFMA2 vs smem W2; store fp16.
// ---------------------------------------------------------------------------
#define NSTRIDE 68
__global__ __launch_bounds__(256) void fused_layer2_kernel(
    const __half* __restrict__ F, const float* __restrict__ W2,
    const float* __restrict__ b1, __half* __restrict__ Y, int n) {
    __shared__ float Ns[32 * NSTRIDE];
    __shared__ float Ws[64 * 32];
    __shared__ float bs[64];

    int tid = threadIdx.x;
    for (int i = tid; i < 64 * 32; i += 256) Ws[i] = W2[i];
    if (tid < 64) bs[tid] = b1[tid];
    __syncthreads();

    int nl = tid >> 3;          // local node 0..31
    int lane = tid & 7;         // 8 lanes per node
    int node = blockIdx.x * 32 + nl;

    float acc[8];
#pragma unroll
    for (int j = 0; j < 8; j++) acc[j] = 0.f;

    if (node < n) {
        int s = g_rs[node], e = g_rs[node + 1];
        int i = s;
#pragma unroll 2
        for (; i + 4 <= e; i += 4) {   // 4 LDG.128 in flight per group
            int s0 = __ldg(g_esrc + i),     s1 = __ldg(g_esrc + i + 1);
            int s2 = __ldg(g_esrc + i + 2), s3 = __ldg(g_esrc + i + 3);
            int4 v0 = *(const int4*)(F + (size_t)s0 * 64 + lane * 8);
            int4 v1 = *(const int4*)(F + (size_t)s1 * 64 + lane * 8);
            int4 v2 = *(const int4*)(F + (size_t)s2 * 64 + lane * 8);
            int4 v3 = *(const int4*)(F + (size_t)s3 * 64 + lane * 8);
            int4 p0 = hadd2_int4(v0, v1);   // one fp16 rounding level
            int4 p1 = hadd2_int4(v2, v3);
            acc8h(acc, p0);
            acc8h(acc, p1);
        }
        for (; i < e; i++) {
            int si = __ldg(g_esrc + i);
            int4 v = *(const int4*)(F + (size_t)si * 64 + lane * 8);
            acc8h(acc, v);
        }
    }
    {
        float* row = Ns + nl * NSTRIDE + lane * 8;
#pragma unroll
        for (int j = 0; j < 8; j++)
            row[j] = fmaxf(acc[j] + bs[lane * 8 + j], 0.f);
    }
    __syncthreads();

    // Phase 2: y[node][lane*4 .. +3] = h[node] @ W2 columns (FFMA2),
    // hrow loaded as float4 per 4 k (LDS.128 broadcast).
    unsigned long long oacc[2] = {0ULL, 0ULL};
    const float* hrow = Ns + nl * NSTRIDE;
#pragma unroll 4
    for (int k = 0; k < 64; k += 4) {
        float4 hv = *(const float4*)(hrow + k);
        float ha[4] = {hv.x, hv.y, hv.z, hv.w};
#pragma unroll
        for (int kk = 0; kk < 4; kk++) {
            unsigned int au = __float_as_uint(ha[kk]);
            unsigned long long a2;
            asm("mov.b64 %0, {%1, %1};" : "=l"(a2) : "r"(au));
            unsigned long long w0 =
                *(const unsigned long long*)(Ws + (k + kk) * 32 + lane * 4);
            unsigned long long w1 =
                *(const unsigned long long*)(Ws + (k + kk) * 32 + lane * 4 + 2);
            FMA2(oacc[0], a2, w0);
            FMA2(oacc[1], a2, w1);
        }
    }
    if (node < n) {
        unsigned int l0, h0, l1, h1;
        asm("mov.b64 {%0, %1}, %2;" : "=r"(l0), "=r"(h0) : "l"(oacc[0]));
        asm("mov.b64 {%0, %1}, %2;" : "=r"(l1), "=r"(h1) : "l"(oacc[1]));
        __half2 p0 = __floats2half2_rn(__uint_as_float(l0), __uint_as_float(h0));
        __half2 p1 = __floats2half2_rn(__uint_as_float(l1), __uint_as_float(h1));
        __half* yr = Y + (size_t)node * 32 + lane * 4;
        *(int2*)yr = make_int2(*(int*)&p0, *(int*)&p1);
    }
}

// ---------------------------------------------------------------------------
// Final gather: 4 lanes x 8 halves per node, b2-init, 4-edge groups
// (unroll 2), one-level fp16 pairing, fp32 float4 stores.
// ---------------------------------------------------------------------------
__global__ void gather32h_kernel(const __half* __restrict__ F,
                                 const float* __restrict__ b2,
                                 float* __restrict__ O, int n) {
    int g = blockIdx.x * blockDim.x + threadIdx.x;
    int node = g >> 2, lane = g & 3;
    if (node >= n) return;
    int s = g_rs[node], e = g_rs[node + 1];
    float acc[8];
    {
        float4 blo = *(const float4*)(b2 + lane * 8);
        float4 bhi = *(const float4*)(b2 + lane * 8 + 4);
        acc[0] = blo.x; acc[1] = blo.y; acc[2] = blo.z; acc[3] = blo.w;
        acc[4] = bhi.x; acc[5] = bhi.y; acc[6] = bhi.z; acc[7] = bhi.w;
    }
    int i = s;
#pragma unroll 2
    for (; i + 4 <= e; i += 4) {
        int s0 = __ldg(g_esrc + i),     s1 = __ldg(g_esrc + i + 1);
        int s2 = __ldg(g_esrc + i + 2), s3 = __ldg(g_esrc + i + 3);
        int4 v0 = *(const int4*)(F + (size_t)s0 * 32 + lane * 8);
        int4 v1 = *(const int4*)(F + (size_t)s1 * 32 + lane * 8);
        int4 v2 = *(const int4*)(F + (size_t)s2 * 32 + lane * 8);
        int4 v3 = *(const int4*)(F + (size_t)s3 * 32 + lane * 8);
        int4 p0 = hadd2_int4(v0, v1);
        int4 p1 = hadd2_int4(v2, v3);
        acc8h(acc, p0);
        acc8h(acc, p1);
    }
    for (; i < e; i++) {
        int si = __ldg(g_esrc + i);
        int4 v = *(const int4*)(F + (size_t)si * 32 + lane * 8);
        acc8h(acc, v);
    }
    float* op = O + (size_t)node * 32 + lane * 8;
    *(float4*)op       = make_float4(acc[0], acc[1], acc[2], acc[3]);
    *(float4*)(op + 4) = make_float4(acc[4], acc[5], acc[6], acc[7]);
}

// ---------------------------------------------------------------------------
// kernel_launch (5 launches)
// ---------------------------------------------------------------------------
extern "C" void kernel_launch(void* const* d_in, const int* in_sizes, int n_in,
                              void* d_out, int out_size) {
    const float* features = (const float*)d_in[0];
    const int*   src      = (const int*)d_in[1];
    const int*   dst      = (const int*)d_in[2];
    const float* W1       = (const float*)d_in[3];
    const float* b1       = (const float*)d_in[4];
    const float* W2       = (const float*)d_in[5];
    const float* b2       = (const float*)d_in[6];
    float*       out      = (float*)d_out;

    int n_nodes = in_sizes[0] / 64;
    int n_edges = in_sizes[1];

    void *pf1, *pf2;
    cudaGetSymbolAddress(&pf1, g_f1h);
    cudaGetSymbolAddress(&pf2, g_f2h);
    __half* f1h = (__half*)pf1;
    __half* f2h = (__half*)pf2;

    int nchunk = (n_nodes + 1023) / 1024;
    int tb = (n_nodes + 127) / 128;
    int hb = (n_edges + 1023) / 1024;  // 128 thr * 8 edges

    // 1) transform1 + histogram (independent; overlapped in one launch)
    t1_hist_kernel<<<tb + hb, 128>>>(features, W1, f1h, dst, n_nodes, n_edges, tb);

    // 2) single-pass scan -> rs/cur (also restores cnt to 0)
    scan_all_kernel<<<nchunk, 256>>>(n_nodes, n_edges);

    // 3) placement (also resets scan flags)
    {
        int nthr = (n_edges + 7) / 8;
        place_kernel<<<(nthr + 255) / 256, 256>>>(src, dst, n_edges);
    }

    // 4) fused layer 2: gather f1h -> relu(+b1) -> @W2 -> f2h
    fused_layer2_kernel<<<(n_nodes + 31) / 32, 256>>>(f1h, W2, b1, f2h, n_nodes);

    // 5) out = b2 + segment_sum(f2h[src] -> dst)
    gather32h_kernel<<<(n_nodes * 4 + 255) / 256, 256>>>(f2h, b2, out, n_nodes);
}

// round 15
// speedup vs baseline: 1.1115x; 1.0066x over previous
#include <cuda_runtime.h>
#include <cuda_fp16.h>
#include <cstddef>

#define NMAX 100000
#define EMAX 1600000
#define NCHUNK_MAX ((NMAX + 1023) / 1024 + 1)

// Scratch (__device__ globals; allocation-free rule; zero-initialized at load)
__device__ __half g_f1h[NMAX * 64];   // features @ W1 (fp16 storage)
__device__ __half g_f2h[NMAX * 32];   // relu(agg + b1) @ W2 (fp16 storage)
__device__ int    g_cnt[NMAX];        // in-degree histogram (self-restoring to 0)
__device__ int    g_rs[NMAX + 4];     // CSR row starts
__device__ int    g_cur[NMAX + 4];    // placement cursors
__device__ int    g_esrc[EMAX];       // CSR src lists grouped by dst
__device__ int    g_bsum[NCHUNK_MAX]; // per-1024-chunk sums
__device__ int    g_flag[NCHUNK_MAX]; // publish flags (reset by place_kernel)

#define FMA2(acc_, a_, b_) \
    asm("fma.rn.f32x2 %0, %1, %2, %0;" : "+l"(acc_) : "l"(a_), "l"(b_))

// Packed fp16 pairwise add: 4 values per instruction
__device__ __forceinline__ int4 hadd2_int4(int4 a, int4 b) {
    int4 r;
    asm("add.rn.f16x2 %0, %1, %2;" : "=r"(r.x) : "r"(a.x), "r"(b.x));
    asm("add.rn.f16x2 %0, %1, %2;" : "=r"(r.y) : "r"(a.y), "r"(b.y));
    asm("add.rn.f16x2 %0, %1, %2;" : "=r"(r.z) : "r"(a.z), "r"(b.z));
    asm("add.rn.f16x2 %0, %1, %2;" : "=r"(r.w) : "r"(a.w), "r"(b.w));
    return r;
}

// Accumulate 8 halves (int4) into 8 fp32 accumulators
__device__ __forceinline__ void acc8h(float* acc, int4 v) {
    __half2 h0 = *(__half2*)&v.x, h1 = *(__half2*)&v.y;
    __half2 h2 = *(__half2*)&v.z, h3 = *(__half2*)&v.w;
    float2 f0 = __half22float2(h0), f1 = __half22float2(h1);
    float2 f2 = __half22float2(h2), f3 = __half22float2(h3);
    acc[0] += f0.x; acc[1] += f0.y; acc[2] += f1.x; acc[3] += f1.y;
    acc[4] += f2.x; acc[5] += f2.y; acc[6] += f3.x; acc[7] += f3.y;
}

// ---------------------------------------------------------------------------
// Fused: transform1 (blocks [0, tb)) + histogram (blocks [tb, tb+hb)).
// ---------------------------------------------------------------------------
__global__ __launch_bounds__(128) void t1_hist_kernel(
    const float* __restrict__ X, const float* __restrict__ W,
    __half* __restrict__ Y, const int* __restrict__ dst,
    int n, int n_edges, int tb) {
    __shared__ float As[128 * 64];
    __shared__ float Ws[64 * 64];
    int tid = threadIdx.x;

    if (blockIdx.x >= tb) {
        // ---- histogram part: 8 edges/thread fire-and-forget REDs ----
        int hb = blockIdx.x - tb;
        int base = (hb * 128 + tid) * 8;
        if (base + 8 <= n_edges) {
            int4 d0 = *(const int4*)(dst + base);
            int4 d1 = *(const int4*)(dst + base + 4);
            atomicAdd(&g_cnt[d0.x], 1); atomicAdd(&g_cnt[d0.y], 1);
            atomicAdd(&g_cnt[d0.z], 1); atomicAdd(&g_cnt[d0.w], 1);
            atomicAdd(&g_cnt[d1.x], 1); atomicAdd(&g_cnt[d1.y], 1);
            atomicAdd(&g_cnt[d1.z], 1); atomicAdd(&g_cnt[d1.w], 1);
        } else {
            for (int j = 0; j < 8; j++)
                if (base + j < n_edges) atomicAdd(&g_cnt[dst[base + j]], 1);
        }
        return;
    }

    // ---- transform part: 128-row tile, thread = 8 rows x 8 cols ----
    for (int i = tid; i < 64 * 64; i += 128) Ws[i] = W[i];
    __syncthreads();

    int blk = blockIdx.x * 128;
#pragma unroll
    for (int i = 0; i < 16; i++) {
        int idx = i * 128 + tid;
        int row = idx >> 4, c = idx & 15;
        int gr = blk + row;
        float4 v = make_float4(0.f, 0.f, 0.f, 0.f);
        if (gr < n) v = *(const float4*)(X + (size_t)gr * 64 + c * 4);
        float vv[4] = {v.x, v.y, v.z, v.w};
        int rm = row & 31;
#pragma unroll
        for (int j = 0; j < 4; j++)
            As[row * 64 + ((c * 4 + j) ^ rm)] = vv[j];
    }
    __syncthreads();

    int tr = tid >> 3, tc = tid & 7;
    unsigned long long acc[8][4];
#pragma unroll
    for (int r = 0; r < 8; r++)
#pragma unroll
        for (int p = 0; p < 4; p++) acc[r][p] = 0ULL;

    int rowoff[8], rmask[8];
#pragma unroll
    for (int r = 0; r < 8; r++) {
        int row = tr * 8 + r;
        rowoff[r] = row * 64;
        rmask[r] = row & 31;
    }

#pragma unroll 4
    for (int k = 0; k < 64; k++) {
        unsigned long long b[4];
#pragma unroll
        for (int p = 0; p < 4; p++)
            b[p] = *(const unsigned long long*)(Ws + k * 64 + tc * 8 + 2 * p);
#pragma unroll
        for (int r = 0; r < 8; r++) {
            float a = As[rowoff[r] + (k ^ rmask[r])];
            unsigned int au = __float_as_uint(a);
            unsigned long long a2;
            asm("mov.b64 %0, {%1, %1};" : "=l"(a2) : "r"(au));
#pragma unroll
            for (int p = 0; p < 4; p++) FMA2(acc[r][p], a2, b[p]);
        }
    }

#pragma unroll
    for (int r = 0; r < 8; r++) {
        int gr = blk + tr * 8 + r;
        if (gr >= n) continue;
        __half* yr = Y + (size_t)gr * 64 + tc * 8;
        unsigned int h[4];
#pragma unroll
        for (int p = 0; p < 4; p++) {
            unsigned int lo, hi;
            asm("mov.b64 {%0, %1}, %2;" : "=r"(lo), "=r"(hi) : "l"(acc[r][p]));
            __half2 hp = __floats2half2_rn(__uint_as_float(lo), __uint_as_float(hi));
            h[p] = *(unsigned int*)&hp;
        }
        *(int4*)yr = make_int4((int)h[0], (int)h[1], (int)h[2], (int)h[3]);
    }
}

// ---------------------------------------------------------------------------
// Single-pass scan: publish chunk sum, spin for predecessors, write rs/cur,
// re-zero own cnt chunk. Grid = nchunk (<=99) < #SMs -> spin is safe.
// ---------------------------------------------------------------------------
__global__ __launch_bounds__(256) void scan_all_kernel(int n, int n_edges) {
    __shared__ int red[256];
    __shared__ int ws[8];
    int b = blockIdx.x, t = threadIdx.x;
    int i = b * 1024 + t * 4;

    int4 v = make_int4(0, 0, 0, 0);
    bool full = (i + 3 < n);
    if (full) {
        v = *(const int4*)(g_cnt + i);
        *(int4*)(g_cnt + i) = make_int4(0, 0, 0, 0);
    } else {
        int tmp[4] = {0, 0, 0, 0};
        for (int j = 0; j < 4; j++)
            if (i + j < n) { tmp[j] = g_cnt[i + j]; g_cnt[i + j] = 0; }
        v = make_int4(tmp[0], tmp[1], tmp[2], tmp[3]);
    }
    int tsum = (v.x + v.y) + (v.z + v.w);

    red[t] = tsum;
    __syncthreads();
    for (int off = 128; off > 0; off >>= 1) {
        if (t < off) red[t] += red[t + off];
        __syncthreads();
    }
    if (t == 0) {
        g_bsum[b] = red[0];
        __threadfence();
        atomicExch(&g_flag[b], 1);
    }
    __syncthreads();

    int lane = t & 31, wid = t >> 5;
    int p = tsum;
#pragma unroll
    for (int o = 1; o < 32; o <<= 1) {
        int x = __shfl_up_sync(0xffffffffu, p, o);
        if (lane >= o) p += x;
    }
    if (lane == 31) ws[wid] = p;
    __syncthreads();
    if (t == 0) {
        int r = 0;
        for (int w = 0; w < 8; w++) { int x = ws[w]; ws[w] = r; r += x; }
    }
    __syncthreads();

    int part = 0;
    if (t < b) {
        while (atomicAdd(&g_flag[t], 0) == 0) {}
        __threadfence();
        part = g_bsum[t];
    }
    red[t] = part;
    __syncthreads();
    for (int off = 128; off > 0; off >>= 1) {
        if (t < off) red[t] += red[t + off];
        __syncthreads();
    }
    int base = red[0];

    int ex = (p - tsum) + ws[wid] + base;
    int4 pre;
    pre.x = ex;
    pre.y = ex + v.x;
    pre.z = pre.y + v.y;
    pre.w = pre.z + v.z;
    if (full) {
        *(int4*)(g_rs + i) = pre;
        *(int4*)(g_cur + i) = pre;
    } else {
        int pr[4] = {pre.x, pre.y, pre.z, pre.w};
        for (int j = 0; j < 4; j++)
            if (i + j < n) { g_rs[i + j] = pr[j]; g_cur[i + j] = pr[j]; }
    }
    if (b == 0 && t == 0) g_rs[n] = n_edges;
}

// ---------------------------------------------------------------------------
// Placement: 8 edges/thread; also resets g_flag for next replay.
// ---------------------------------------------------------------------------
__global__ void place_kernel(const int* __restrict__ src,
                             const int* __restrict__ dst, int n_edges) {
    if (blockIdx.x == 0 && threadIdx.x < NCHUNK_MAX) g_flag[threadIdx.x] = 0;
    int base = (blockIdx.x * blockDim.x + threadIdx.x) * 8;
    if (base + 8 <= n_edges) {
        int4 d0 = *(const int4*)(dst + base);
        int4 d1 = *(const int4*)(dst + base + 4);
        int4 s0 = *(const int4*)(src + base);
        int4 s1 = *(const int4*)(src + base + 4);
        int dd[8] = {d0.x, d0.y, d0.z, d0.w, d1.x, d1.y, d1.z, d1.w};
        int ss[8] = {s0.x, s0.y, s0.z, s0.w, s1.x, s1.y, s1.z, s1.w};
#pragma unroll
        for (int j = 0; j < 8; j++) {
            int p = atomicAdd(&g_cur[dd[j]], 1);
            g_esrc[p] = ss[j];
        }
    } else {
        for (int j = 0; j < 8; j++) {
            int e = base + j;
            if (e < n_edges) {
                int p = atomicAdd(&g_cur[dst[e]], 1);
                g_esrc[p] = src[e];
            }
        }
    }
}

// ---------------------------------------------------------------------------
// Fused layer 2: block = 256 thr = 32 nodes x 8 lanes. Gather with 4-edge
// groups (unroll 2), one-level fp16 pairing, fp32 accumulate; relu(+b1) ->
// smem row (stride 68). Phase coupling is WARP-LOCAL (each warp's 4 nodes
// are produced and consumed by the same warp) -> __syncwarp, not
// __syncthreads: no max-of-32 straggler wait.
// ---------------------------------------------------------------------------
#define NSTRIDE 68
__global__ __launch_bounds__(256) void fused_layer2_kernel(
    const __half* __restrict__ F, const float* __restrict__ W2,
    const float* __restrict__ b1, __half* __restrict__ Y, int n) {
    __shared__ float Ns[32 * NSTRIDE];
    __shared__ float Ws[64 * 32];
    __shared__ float bs[64];

    int tid = threadIdx.x;
    for (int i = tid; i < 64 * 32; i += 256) Ws[i] = W2[i];
    if (tid < 64) bs[tid] = b1[tid];
    __syncthreads();

    int nl = tid >> 3;          // local node 0..31
    int lane = tid & 7;         // 8 lanes per node
    int node = blockIdx.x * 32 + nl;

    float acc[8];
#pragma unroll
    for (int j = 0; j < 8; j++) acc[j] = 0.f;

    if (node < n) {
        int s = g_rs[node], e = g_rs[node + 1];
        int i = s;
#pragma unroll 2
        for (; i + 4 <= e; i += 4) {   // 4 LDG.128 in flight per group
            int s0 = __ldg(g_esrc + i),     s1 = __ldg(g_esrc + i + 1);
            int s2 = __ldg(g_esrc + i + 2), s3 = __ldg(g_esrc + i + 3);
            int4 v0 = *(const int4*)(F + (size_t)s0 * 64 + lane * 8);
            int4 v1 = *(const int4*)(F + (size_t)s1 * 64 + lane * 8);
            int4 v2 = *(const int4*)(F + (size_t)s2 * 64 + lane * 8);
            int4 v3 = *(const int4*)(F + (size_t)s3 * 64 + lane * 8);
            int4 p0 = hadd2_int4(v0, v1);   // one fp16 rounding level
            int4 p1 = hadd2_int4(v2, v3);
            acc8h(acc, p0);
            acc8h(acc, p1);
        }
        for (; i < e; i++) {
            int si = __ldg(g_esrc + i);
            int4 v = *(const int4*)(F + (size_t)si * 64 + lane * 8);
            acc8h(acc, v);
        }
    }
    {
        float* row = Ns + nl * NSTRIDE + lane * 8;
#pragma unroll
        for (int j = 0; j < 8; j++)
            row[j] = fmaxf(acc[j] + bs[lane * 8 + j], 0.f);
    }
    __syncwarp();   // phase coupling is warp-local: wait for max-of-4, not 32

    // Phase 2: y[node][lane*4 .. +3] = h[node] @ W2 columns (FFMA2),
    // hrow loaded as float4 per 4 k (LDS.128 broadcast within group).
    unsigned long long oacc[2] = {0ULL, 0ULL};
    const float* hrow = Ns + nl * NSTRIDE;
#pragma unroll 4
    for (int k = 0; k < 64; k += 4) {
        float4 hv = *(const float4*)(hrow + k);
        float ha[4] = {hv.x, hv.y, hv.z, hv.w};
#pragma unroll
        for (int kk = 0; kk < 4; kk++) {
            unsigned int au = __float_as_uint(ha[kk]);
            unsigned long long a2;
            asm("mov.b64 %0, {%1, %1};" : "=l"(a2) : "r"(au));
            unsigned long long w0 =
                *(const unsigned long long*)(Ws + (k + kk) * 32 + lane * 4);
            unsigned long long w1 =
                *(const unsigned long long*)(Ws + (k + kk) * 32 + lane * 4 + 2);
            FMA2(oacc[0], a2, w0);
            FMA2(oacc[1], a2, w1);
        }
    }
    if (node < n) {
        unsigned int l0, h0, l1, h1;
        asm("mov.b64 {%0, %1}, %2;" : "=r"(l0), "=r"(h0) : "l"(oacc[0]));
        asm("mov.b64 {%0, %1}, %2;" : "=r"(l1), "=r"(h1) : "l"(oacc[1]));
        __half2 p0 = __floats2half2_rn(__uint_as_float(l0), __uint_as_float(h0));
        __half2 p1 = __floats2half2_rn(__uint_as_float(l1), __uint_as_float(h1));
        __half* yr = Y + (size_t)node * 32 + lane * 4;
        *(int2*)yr = make_int2(*(int*)&p0, *(int*)&p1);
    }
}

// ---------------------------------------------------------------------------
// Final gather: 8 lanes/node, 2 edges per iteration (lane = parity p x col-
// quarter q). Warp spans 4 nodes (max-of-4 divergence, half the iterations).
// One shfl_xor(4) merge per node; +b2 post-reduction; lanes 0-3 store.
// ---------------------------------------------------------------------------
__global__ __launch_bounds__(256) void gather32h_kernel(
    const __half* __restrict__ F, const float* __restrict__ b2,
    float* __restrict__ O, int n) {
    int tid = blockIdx.x * blockDim.x + threadIdx.x;
    int node = tid >> 3;
    int lane = tid & 7;
    int p = lane >> 2;          // edge parity (0/1)
    int q = lane & 3;           // column quarter
    if (node >= n) return;

    int s = g_rs[node], e = g_rs[node + 1];
    float acc[8];
#pragma unroll
    for (int j = 0; j < 8; j++) acc[j] = 0.f;

    int i = s + p;              // half p handles edges s+p, s+p+2, ...
#pragma unroll 2
    for (; i + 2 < e; i += 4) { // 2 edges per lane-iter (fp16-paired)
        int s0 = __ldg(g_esrc + i);
        int s1 = __ldg(g_esrc + i + 2);
        int4 v0 = *(const int4*)(F + (size_t)s0 * 32 + q * 8);
        int4 v1 = *(const int4*)(F + (size_t)s1 * 32 + q * 8);
        int4 pr = hadd2_int4(v0, v1);
        acc8h(acc, pr);
    }
    if (i < e) {
        int si = __ldg(g_esrc + i);
        int4 v = *(const int4*)(F + (size_t)si * 32 + q * 8);
        acc8h(acc, v);
    }

    // merge the two parity halves (same q, p=0 and p=1 are 4 apart)
#pragma unroll
    for (int j = 0; j < 8; j++)
        acc[j] += __shfl_xor_sync(0xffffffffu, acc[j], 4);

    if (p == 0) {
        float4 blo = *(const float4*)(b2 + q * 8);
        float4 bhi = *(const float4*)(b2 + q * 8 + 4);
        float* op = O + (size_t)node * 32 + q * 8;
        *(float4*)op = make_float4(acc[0] + blo.x, acc[1] + blo.y,
                                   acc[2] + blo.z, acc[3] + blo.w);
        *(float4*)(op + 4) = make_float4(acc[4] + bhi.x, acc[5] + bhi.y,
                                         acc[6] + bhi.z, acc[7] + bhi.w);
    }
}

// ---------------------------------------------------------------------------
// kernel_launch (5 launches)
// ---------------------------------------------------------------------------
extern "C" void kernel_launch(void* const* d_in, const int* in_sizes, int n_in,
                              void* d_out, int out_size) {
    const float* features = (const float*)d_in[0];
    const int*   src      = (const int*)d_in[1];
    const int*   dst      = (const int*)d_in[2];
    const float* W1       = (const float*)d_in[3];
    const float* b1       = (const float*)d_in[4];
    const float* W2       = (const float*)d_in[5];
    const float* b2       = (const float*)d_in[6];
    float*       out      = (float*)d_out;

    int n_nodes = in_sizes[0] / 64;
    int n_edges = in_sizes[1];

    void *pf1, *pf2;
    cudaGetSymbolAddress(&pf1, g_f1h);
    cudaGetSymbolAddress(&pf2, g_f2h);
    __half* f1h = (__half*)pf1;
    __half* f2h = (__half*)pf2;

    int nchunk = (n_nodes + 1023) / 1024;
    int tb = (n_nodes + 127) / 128;
    int hb = (n_edges + 1023) / 1024;  // 128 thr * 8 edges

    // 1) transform1 + histogram (independent; overlapped in one launch)
    t1_hist_kernel<<<tb + hb, 128>>>(features, W1, f1h, dst, n_nodes, n_edges, tb);

    // 2) single-pass scan -> rs/cur (also restores cnt to 0)
    scan_all_kernel<<<nchunk, 256>>>(n_nodes, n_edges);

    // 3) placement (also resets scan flags)
    {
        int nthr = (n_edges + 7) / 8;
        place_kernel<<<(nthr + 255) / 256, 256>>>(src, dst, n_edges);
    }

    // 4) fused layer 2: gather f1h -> relu(+b1) -> @W2 -> f2h
    fused_layer2_kernel<<<(n_nodes + 31) / 32, 256>>>(f1h, W2, b1, f2h, n_nodes);

    // 5) out = b2 + segment_sum(f2h[src] -> dst)
    gather32h_kernel<<<(n_nodes * 8 + 255) / 256, 256>>>(f2h, b2, out, n_nodes);
}